// round 1
// baseline (speedup 1.0000x reference)
#include <cuda_runtime.h>
#include <math.h>

// Problem constants
#define B_   8
#define P_   16384
#define M_   16
#define CI_  16
#define CO_  32
#define W_   17
#define K_   272          // W_*CI_
#define WFS  276          // padded k-stride for Wf (bank-conflict-free LDS.128)

static __device__ __forceinline__ float elu1(float x) {
    return (x > 0.0f) ? x : expm1f(x);
}

// smem layout (floats):
//   Wf   [32][276]              = 8832
//   wres [32][16]               = 512
//   per-warp region (8 warps), each 2592 floats:
//     g    [8][272] = 2176
//     ww   [16][17] = 272   (mask folded in)
//     ownx [8][16]  = 128
//     nb   [16]     = 16 (ints)
// total = 9344 + 8*2592 = 30080 floats = 120320 bytes

__global__ void __launch_bounds__(256, 1)
fused_conv_kernel(const float* __restrict__ in_pc,
                  const float* __restrict__ weights,
                  const float* __restrict__ bias,
                  const float* __restrict__ w_weights,
                  const float* __restrict__ weight_res,
                  const int*   __restrict__ neighbor_id,
                  float*       __restrict__ out)
{
    constexpr float SQ_CONV = 0.70710678118654752440f;  // sqrt(1 - 0.5)
    constexpr float SQ_RES  = 0.70710678118654752440f;  // sqrt(0.5)

    extern __shared__ float sm[];
    float* Wf   = sm;               // [32][WFS]
    float* wres = sm + 32 * WFS;    // [32][16]

    const int tid  = threadIdx.x;
    const int warp = tid >> 5;
    const int lane = tid & 31;

    float* wbase = sm + 32 * WFS + 512 + warp * 2592;
    float* g_s   = wbase;           // [8][272]
    float* ww_s  = wbase + 2176;    // [16][17]
    float* ownx  = wbase + 2448;    // [8][16]
    int*   nb_s  = (int*)(wbase + 2576); // [16]

    // ---- block-shared weight staging ----
    // weights[w][o*16+i]  ->  Wf[o][w*16+i]
    for (int idx = tid; idx < W_ * 512; idx += 256) {
        int w   = idx / 512;
        int rem = idx - w * 512;
        int o   = rem >> 4;
        int i   = rem & 15;
        Wf[o * WFS + w * 16 + i] = weights[idx];
    }
    for (int idx = tid; idx < 512; idx += 256) wres[idx] = weight_res[idx];
    __syncthreads();

    const int p = blockIdx.x * 8 + warp;

    // ---- per-warp staging: neighbor ids, masked ww, own-point x ----
    if (lane < 16) nb_s[lane] = neighbor_id[p * M_ + lane];
    __syncwarp();

    for (int idx = lane; idx < K_; idx += 32) {
        int m = idx / 17;                     // layout [m][w]
        float v = w_weights[(size_t)p * K_ + idx];
        ww_s[idx] = (nb_s[m] == P_) ? 0.0f : v;
    }
    {
        const int b  = lane >> 2;
        const int ig = lane & 3;
        float4 x4 = *(const float4*)&in_pc[((size_t)b * P_ + p) * CI_ + ig * 4];
        *(float4*)&ownx[b * 16 + ig * 4] = x4;
    }
    __syncwarp();

    // ---- stage A: g[b][w*16+i] = sum_m ww[m][w] * x[b, nb(m), i] ----
    const int b  = lane >> 2;
    const int ig = lane & 3;

    float gacc[17][4];
    #pragma unroll
    for (int w = 0; w < 17; w++) {
        gacc[w][0] = 0.f; gacc[w][1] = 0.f; gacc[w][2] = 0.f; gacc[w][3] = 0.f;
    }

    const float* xbase = in_pc + (size_t)b * P_ * CI_ + ig * 4;
    #pragma unroll 4
    for (int m = 0; m < M_; m++) {
        int nb  = nb_s[m];
        int nbc = (nb == P_) ? 0 : nb;        // ww already 0 for pad -> exact zero contribution
        float4 x4 = *(const float4*)(xbase + (size_t)nbc * CI_);
        #pragma unroll
        for (int w = 0; w < 17; w++) {
            float f = ww_s[m * 17 + w];
            gacc[w][0] += f * x4.x;
            gacc[w][1] += f * x4.y;
            gacc[w][2] += f * x4.z;
            gacc[w][3] += f * x4.w;
        }
    }

    #pragma unroll
    for (int w = 0; w < 17; w++) {
        *(float4*)&g_s[b * K_ + w * 16 + ig * 4] =
            make_float4(gacc[w][0], gacc[w][1], gacc[w][2], gacc[w][3]);
    }
    __syncwarp();

    // ---- stage B: lane = o.  out[b][o] = sum_k g[b][k] * Wf[o][k] ----
    float acc[8];
    #pragma unroll
    for (int j = 0; j < 8; j++) acc[j] = 0.f;

    const float* wfrow = Wf + lane * WFS;
    #pragma unroll 4
    for (int k4 = 0; k4 < 68; k4++) {
        float4 wv = *(const float4*)(wfrow + k4 * 4);
        #pragma unroll
        for (int bb = 0; bb < 8; bb++) {
            float4 gv = *(const float4*)&g_s[bb * K_ + k4 * 4];
            acc[bb] += wv.x * gv.x + wv.y * gv.y + wv.z * gv.z + wv.w * gv.w;
        }
    }

    // ---- residual + ELU + store ----
    float wr[16];
    #pragma unroll
    for (int i = 0; i < 16; i++) wr[i] = wres[lane * 16 + i];
    float bi = bias[(size_t)p * CO_ + lane];

    #pragma unroll
    for (int bb = 0; bb < 8; bb++) {
        float r = 0.f;
        #pragma unroll
        for (int i = 0; i < 16; i++) r += wr[i] * ownx[bb * 16 + i];
        float c = acc[bb] + bi;
        float e = elu1(c);
        out[((size_t)bb * P_ + p) * CO_ + lane] = e * SQ_CONV + r * SQ_RES;
    }
}

extern "C" void kernel_launch(void* const* d_in, const int* in_sizes, int n_in,
                              void* d_out, int out_size)
{
    const float* in_pc       = nullptr;
    const float* weights     = nullptr;
    const float* bias        = nullptr;
    const float* w_weights   = nullptr;
    const float* weight_res  = nullptr;
    const int*   neighbor_id = nullptr;

    for (int i = 0; i < n_in; i++) {
        switch (in_sizes[i]) {
            case 2097152: in_pc       = (const float*)d_in[i]; break; // (8,16384,16)
            case 8704:    weights     = (const float*)d_in[i]; break; // (17,512)
            case 524288:  bias        = (const float*)d_in[i]; break; // (16384,32)
            case 4456448: w_weights   = (const float*)d_in[i]; break; // (16384,16,17)
            case 512:     weight_res  = (const float*)d_in[i]; break; // (32,16)
            case 262144:  neighbor_id = (const int*)d_in[i];   break; // (16384,16)
            default: break;
        }
    }

    const int smem_bytes = 30080 * 4; // 120320
    cudaFuncSetAttribute(fused_conv_kernel,
                         cudaFuncAttributeMaxDynamicSharedMemorySize, smem_bytes);

    fused_conv_kernel<<<P_ / 8, 256, smem_bytes>>>(
        in_pc, weights, bias, w_weights, weight_res, neighbor_id, (float*)d_out);
}

// round 2
// speedup vs baseline: 1.0138x; 1.0138x over previous
#include <cuda_runtime.h>
#include <math.h>

// Problem constants
#define B_   8
#define P_   16384
#define M_   16
#define CI_  16
#define CO_  32
#define W_   17
#define WSLOT 18          // 17 conv w-slots + 1 residual slot
#define OSTRIDE 288       // WSLOT*16 floats per output row in Wf
#define WWS  20           // padded per-m stride for ww (16B-aligned float4 loads)

// smem (floats):
//   Wf   [32][288]  = 9216   (Wf[o][w][i], w=17 -> weight_res[o][i])
//   per-warp (4 warps), 336 floats each:
//     ww  [16][20]  = 320   (mask folded in)
//     nb  [16]      = 16 (ints)
// total = 9216 + 4*336 = 10560 floats = 42240 bytes -> 4 CTAs/SM (reg-bound)

__global__ void __launch_bounds__(128, 4)
fused_conv_kernel(const float* __restrict__ in_pc,
                  const float* __restrict__ weights,
                  const float* __restrict__ bias,
                  const float* __restrict__ w_weights,
                  const float* __restrict__ weight_res,
                  const int*   __restrict__ neighbor_id,
                  float*       __restrict__ out)
{
    constexpr float SQ_CONV = 0.70710678118654752440f;
    constexpr float SQ_RES  = 0.70710678118654752440f;

    extern __shared__ float sm[];
    float* Wf = sm;                                   // [32][288]

    const int tid  = threadIdx.x;
    const int warp = tid >> 5;
    const int lane = tid & 31;

    float* ww_s = sm + 32 * OSTRIDE + warp * 336;     // [16][20]
    int*   nb_s = (int*)(ww_s + 320);                 // [16]

    // ---- stage weights: Wf[o][w*16+i], slot w=17 holds weight_res ----
    for (int idx = tid; idx < W_ * 512; idx += 128) {
        int w   = idx >> 9;
        int rem = idx & 511;
        int o   = rem >> 4;
        int i   = rem & 15;
        Wf[o * OSTRIDE + w * 16 + i] = weights[idx];
    }
    for (int idx = tid; idx < 512; idx += 128) {
        int o = idx >> 4, i = idx & 15;
        Wf[o * OSTRIDE + 272 + i] = weight_res[idx];
    }

    const int p = blockIdx.x * 4 + warp;

    // ---- per-warp staging: neighbor ids, masked ww ----
    if (lane < 16) nb_s[lane] = neighbor_id[p * M_ + lane];
    __syncwarp();
    for (int idx = lane; idx < 272; idx += 32) {
        int m = idx / 17;
        int w = idx - m * 17;
        float v = w_weights[(size_t)p * 272 + idx];
        ww_s[m * WWS + w] = (nb_s[m] == P_) ? 0.0f : v;
    }
    __syncthreads();   // Wf + ww + nb all visible

    const int b  = lane >> 2;
    const int ig = lane & 3;

    // gacc[w][j]: w=0..16 conv accumulators for this lane's i-chunk,
    // gacc[17] = own x chunk (for residual).
    float gacc[WSLOT][4];
    #pragma unroll
    for (int w = 0; w < 17; w++) {
        gacc[w][0] = 0.f; gacc[w][1] = 0.f; gacc[w][2] = 0.f; gacc[w][3] = 0.f;
    }
    {
        float4 xo = *(const float4*)&in_pc[((size_t)b * P_ + p) * CI_ + ig * 4];
        gacc[17][0] = xo.x; gacc[17][1] = xo.y; gacc[17][2] = xo.z; gacc[17][3] = xo.w;
    }

    // ---- stage A: g[w][i] = sum_m ww[m][w] * x[b, nb(m), i-chunk] ----
    const float* xbase = in_pc + (size_t)b * P_ * CI_ + ig * 4;
    #pragma unroll 4
    for (int m = 0; m < M_; m++) {
        int nb  = nb_s[m];
        int nbc = (nb == P_) ? 0 : nb;      // ww already zeroed for pad
        float4 x4 = *(const float4*)(xbase + (size_t)nbc * CI_);
        const float* wwm = ww_s + m * WWS;
        #pragma unroll
        for (int wg = 0; wg < 4; wg++) {
            float4 wv = *(const float4*)(wwm + wg * 4);
            gacc[wg*4+0][0] += wv.x * x4.x; gacc[wg*4+0][1] += wv.x * x4.y;
            gacc[wg*4+0][2] += wv.x * x4.z; gacc[wg*4+0][3] += wv.x * x4.w;
            gacc[wg*4+1][0] += wv.y * x4.x; gacc[wg*4+1][1] += wv.y * x4.y;
            gacc[wg*4+1][2] += wv.y * x4.z; gacc[wg*4+1][3] += wv.y * x4.w;
            gacc[wg*4+2][0] += wv.z * x4.x; gacc[wg*4+2][1] += wv.z * x4.y;
            gacc[wg*4+2][2] += wv.z * x4.z; gacc[wg*4+2][3] += wv.z * x4.w;
            gacc[wg*4+3][0] += wv.w * x4.x; gacc[wg*4+3][1] += wv.w * x4.y;
            gacc[wg*4+3][2] += wv.w * x4.z; gacc[wg*4+3][3] += wv.w * x4.w;
        }
        float w16 = wwm[16];
        gacc[16][0] += w16 * x4.x; gacc[16][1] += w16 * x4.y;
        gacc[16][2] += w16 * x4.z; gacc[16][3] += w16 * x4.w;
    }

    // ---- stage B: rotate g chunks through the 4 ig lanes; lane owns o-octet ----
    // Round r: this lane holds the chunk originally owned by lane ig^r.
    float acc[8], racc[8];
    #pragma unroll
    for (int oo = 0; oo < 8; oo++) { acc[oo] = 0.f; racc[oo] = 0.f; }

    const int obase = ig * 8;
    const float* wfoct = Wf + obase * OSTRIDE;

    #pragma unroll 1
    for (int r = 0; r < 4; r++) {
        if (r) {
            int mask = (r == 2) ? 3 : 1;   // cum-xor path: 0 ->1 ->2 ->3
            #pragma unroll
            for (int w = 0; w < WSLOT; w++) {
                gacc[w][0] = __shfl_xor_sync(0xffffffffu, gacc[w][0], mask);
                gacc[w][1] = __shfl_xor_sync(0xffffffffu, gacc[w][1], mask);
                gacc[w][2] = __shfl_xor_sync(0xffffffffu, gacc[w][2], mask);
                gacc[w][3] = __shfl_xor_sync(0xffffffffu, gacc[w][3], mask);
            }
        }
        const int chunk = ig ^ r;
        const float* wfb = wfoct + chunk * 4;
        #pragma unroll
        for (int w = 0; w < 17; w++) {
            #pragma unroll
            for (int oo = 0; oo < 8; oo++) {
                float4 wv = *(const float4*)(wfb + oo * OSTRIDE + w * 16);
                acc[oo] += wv.x * gacc[w][0] + wv.y * gacc[w][1]
                         + wv.z * gacc[w][2] + wv.w * gacc[w][3];
            }
        }
        #pragma unroll
        for (int oo = 0; oo < 8; oo++) {
            float4 wv = *(const float4*)(wfb + oo * OSTRIDE + 272);
            racc[oo] += wv.x * gacc[17][0] + wv.y * gacc[17][1]
                      + wv.z * gacc[17][2] + wv.w * gacc[17][3];
        }
    }

    // ---- epilogue: bias + ELU + residual blend, write o-octet ----
    const float* bptr = bias + (size_t)p * CO_ + obase;
    float4 bz0 = *(const float4*)(bptr);
    float4 bz1 = *(const float4*)(bptr + 4);
    float bb[8] = {bz0.x, bz0.y, bz0.z, bz0.w, bz1.x, bz1.y, bz1.z, bz1.w};

    float res[8];
    #pragma unroll
    for (int oo = 0; oo < 8; oo++) {
        float c = acc[oo] + bb[oo];
        float e = (c > 0.0f) ? c : expm1f(c);
        res[oo] = e * SQ_CONV + racc[oo] * SQ_RES;
    }
    float* optr = out + ((size_t)b * P_ + p) * CO_ + obase;
    *(float4*)(optr)     = make_float4(res[0], res[1], res[2], res[3]);
    *(float4*)(optr + 4) = make_float4(res[4], res[5], res[6], res[7]);
}

extern "C" void kernel_launch(void* const* d_in, const int* in_sizes, int n_in,
                              void* d_out, int out_size)
{
    const float* in_pc       = nullptr;
    const float* weights     = nullptr;
    const float* bias        = nullptr;
    const float* w_weights   = nullptr;
    const float* weight_res  = nullptr;
    const int*   neighbor_id = nullptr;

    for (int i = 0; i < n_in; i++) {
        switch (in_sizes[i]) {
            case 2097152: in_pc       = (const float*)d_in[i]; break; // (8,16384,16)
            case 8704:    weights     = (const float*)d_in[i]; break; // (17,512)
            case 524288:  bias        = (const float*)d_in[i]; break; // (16384,32)
            case 4456448: w_weights   = (const float*)d_in[i]; break; // (16384,16,17)
            case 512:     weight_res  = (const float*)d_in[i]; break; // (32,16)
            case 262144:  neighbor_id = (const int*)d_in[i];   break; // (16384,16)
            default: break;
        }
    }

    const int smem_bytes = 10560 * 4; // 42240
    cudaFuncSetAttribute(fused_conv_kernel,
                         cudaFuncAttributeMaxDynamicSharedMemorySize, smem_bytes);

    fused_conv_kernel<<<P_ / 4, 128, smem_bytes>>>(
        in_pc, weights, bias, w_weights, weight_res, neighbor_id, (float*)d_out);
}